// round 13
// baseline (speedup 1.0000x reference)
#include <cuda_runtime.h>
#include <cuda_fp16.h>
#include <cstdint>
#include <cstddef>

#define NB 4096
#define HH 512
#define NSEQ 100
#define NJ 63

// ---------- device scratch ----------
__device__ __align__(1024) __half g_xh [NB * 256];
__device__ __align__(1024) __half g_h0h[2][NB * HH];
__device__ __align__(1024) __half g_h1a[(size_t)(NSEQ + 1) * NB * HH];
__device__ __align__(1024) float  g_c0 [NB * HH];          // tile-order layout
__device__ __align__(1024) float  g_c1 [NB * HH];          // tile-order layout
__device__ __align__(1024) __half g_Wi0p[16 * 128 * 256];
__device__ __align__(1024) __half g_Wp0 [16 * 128 * 512];
__device__ __align__(1024) __half g_Wp1 [16 * 128 * 1024];
__device__ __align__(1024) __half g_fcWh[64 * 512];
__device__ float g_b0p[2048];
__device__ float g_b1p[2048];
__device__ __align__(1024) __half g_x0h[(size_t)2048 * NB]; // epi-order halves
__device__ float g_y2[(size_t)NSEQ * NB * 64];

// ---------- helpers ----------
__device__ __forceinline__ float sigm(float x) { return 1.f / (1.f + expf(-x)); }
__device__ __forceinline__ uint32_t smem_u32(const void* p) {
    uint32_t a;
    asm("{ .reg .u64 t; cvta.to.shared.u64 t, %1; cvt.u32.u64 %0, t; }" : "=r"(a) : "l"(p));
    return a;
}
#define CP16(dst, src) asm volatile("cp.async.cg.shared.global [%0], [%1], 16;" :: "r"((uint32_t)(dst)), "l"(src) : "memory")
#define CP_COMMIT()    asm volatile("cp.async.commit_group;" ::: "memory")
#define CP_WAIT(n)     asm volatile("cp.async.wait_group %0;" :: "n"(n) : "memory")
// deferred arrive that CONSUMES one init-time expected arrival (.noinc!)
#define CPA_MBAR(a)    asm volatile("cp.async.mbarrier.arrive.noinc.shared.b64 [%0];" :: "r"((uint32_t)(a)) : "memory")
#define MBAR_INIT(a, c) asm volatile("mbarrier.init.shared.b64 [%0], %1;" :: "r"((uint32_t)(a)), "r"((uint32_t)(c)) : "memory")
#define MBAR_ARRIVE(a)  asm volatile("mbarrier.arrive.shared.b64 _, [%0];" :: "r"((uint32_t)(a)) : "memory")
// bounded wait: breaks (visible wrong answer) instead of hanging on protocol bugs
#define MBAR_WAIT(a, ph) do {                                                    \
    uint32_t _m = (uint32_t)(a), _p = (uint32_t)(ph), _d = 0;                    \
    for (int _i = 0; _i < 4000000 && !_d; ++_i) {                                \
        asm volatile("{\n\t.reg .pred p;\n\t"                                    \
            "mbarrier.try_wait.parity.acquire.cta.shared::cta.b64 p, [%1], %2, 0x2710;\n\t" \
            "selp.b32 %0,1,0,p;\n\t}" : "=r"(_d) : "r"(_m), "r"(_p) : "memory"); \
    } } while (0)
#define LDSM_X4(r0, r1, r2, r3, a) \
    asm volatile("ldmatrix.sync.aligned.m8n8.x4.shared.b16 {%0,%1,%2,%3}, [%4];" \
        : "=r"(r0), "=r"(r1), "=r"(r2), "=r"(r3) : "r"(a))

__device__ __forceinline__ void hmma(float (&c)[4],
    uint32_t a0, uint32_t a1, uint32_t a2, uint32_t a3, uint32_t b0, uint32_t b1)
{
    asm volatile(
        "mma.sync.aligned.m16n8k16.row.col.f32.f16.f16.f32 "
        "{%0,%1,%2,%3}, {%4,%5,%6,%7}, {%8,%9}, {%0,%1,%2,%3};\n"
        : "+f"(c[0]), "+f"(c[1]), "+f"(c[2]), "+f"(c[3])
        : "r"(a0), "r"(a1), "r"(a2), "r"(a3), "r"(b0), "r"(b1));
}
__device__ __forceinline__ uint32_t sw128(uint32_t off) { return off ^ ((off >> 3) & 0x70); }

// ---------- prologue: col n of tile jt -> orig row (n>>5)*512 + jt*32 + (n&31) ----------
__global__ void pack_weights(
    const float* __restrict__ Wih0, const float* __restrict__ Whh0,
    const float* __restrict__ bih0, const float* __restrict__ bhh0,
    const float* __restrict__ Wih1, const float* __restrict__ Whh1,
    const float* __restrict__ bih1, const float* __restrict__ bhh1,
    const float* __restrict__ fcW)
{
    int i0 = blockIdx.x * blockDim.x + threadIdx.x;
    int st = gridDim.x * blockDim.x;
    for (int i = i0; i < 16 * 128 * 512; i += st) {
        int jt = i >> 16, n = (i >> 9) & 127, k = i & 511;
        int row = (n >> 5) * HH + jt * 32 + (n & 31);
        g_Wp0[i] = __float2half_rn(Whh0[(size_t)row * HH + k]);
    }
    for (int i = i0; i < 16 * 128 * 1024; i += st) {
        int jt = i >> 17, n = (i >> 10) & 127, k = i & 1023;
        int row = (n >> 5) * HH + jt * 32 + (n & 31);
        float v = (k < HH) ? Wih1[(size_t)row * HH + k] : Whh1[(size_t)row * HH + k - HH];
        g_Wp1[i] = __float2half_rn(v);
    }
    for (int i = i0; i < 16 * 128 * 256; i += st) {
        int jt = i >> 15, n = (i >> 8) & 127, k = i & 255;
        int row = (n >> 5) * HH + jt * 32 + (n & 31);
        g_Wi0p[i] = (k < 254) ? __float2half_rn(Wih0[(size_t)row * 254 + k]) : __half(0);
    }
    for (int i = i0; i < 64 * 512; i += st) {
        int j = i >> 9, k = i & 511;
        g_fcWh[i] = (j < NJ) ? __float2half_rn(fcW[(size_t)j * HH + k]) : __half(0);
    }
    for (int i = i0; i < 2048; i += st) {
        int jt = i >> 7, n = i & 127;
        int row = (n >> 5) * HH + jt * 32 + (n & 31);
        g_b0p[i] = bih0[row] + bhh0[row];
        g_b1p[i] = bih1[row] + bhh1[row];
    }
}

__global__ void build_x_init(
    const int* __restrict__ sl, const int* __restrict__ el,
    const float* __restrict__ sc, const float* __restrict__ ec,
    const float* __restrict__ emb)
{
    int i0 = blockIdx.x * blockDim.x + threadIdx.x;
    int st = gridDim.x * blockDim.x;
    for (int i = i0; i < NB * 256; i += st) {
        int b = i >> 8, k = i & 255;
        float v;
        if      (k < 64)  v = emb[sl[b] * 64 + k];
        else if (k < 128) v = emb[el[b] * 64 + (k - 64)];
        else if (k < 191) v = sc[b * 63 + (k - 128)];
        else if (k < 254) v = ec[b * 63 + (k - 191)];
        else              v = 0.f;
        g_xh[i] = __float2half_rn(v);
    }
    __half z = __half(0);
    for (int i = i0; i < NB * HH; i += st) {
        g_h0h[0][i] = z; g_h0h[1][i] = z; g_h1a[i] = z;
        g_c0[i] = 0.f; g_c1[i] = 0.f;
    }
}

// ---------- warp-specialized fused GEMM + gates ----------
// CTA 128x128, 320 threads: warps 0-7 compute (16x128 each), warps 8-9 produce.
// 4-stage cp.async ring with full/empty mbarriers; zero __syncthreads in mainloop.
constexpr int NSTAGE = 4, STGB = 32768;
constexpr int OFF_STG = 1024;
constexpr int OFF_X0  = OFF_STG + NSTAGE * STGB;   // 132096
constexpr int OFF_C   = OFF_X0 + 32768;            // 164864
constexpr int SMEMSZ  = OFF_C + 16384;             // 181248
constexpr int NTHR = 320;

template<int MODE>   // 0: layer0 K=512 (+x0)  1: layer1 K=1024 (+bias)  2: x0 K=256 (+bias)
__device__ __forceinline__ void tile_body(
    const __half* __restrict__ A1, const __half* __restrict__ A2,
    const __half* __restrict__ Wp, const float* __restrict__ addv,
    float* __restrict__ cbuf, void* __restrict__ houtv, char* smem,
    int m0, int jt, int tl)
{
    const uint32_t sb = smem_u32(smem);
    const int tid = threadIdx.x, lane = tid & 31, wid = tid >> 5;
    constexpr int KW  = (MODE == 0) ? 512 : (MODE == 1) ? 1024 : 256;
    constexpr int LDA = (MODE == 2) ? 256 : 512;
    constexpr int NT  = KW / 64;

    if (tid == 0) {
        for (int s = 0; s < NSTAGE; ++s) {
            MBAR_INIT(sb + s * 16, 64);        // full[s]  (64 producer noinc arrivals)
            MBAR_INIT(sb + s * 16 + 8, 256);   // empty[s] (256 consumer arrivals)
        }
        MBAR_INIT(sb + 64, 64);                // epi barrier
    }
    __syncthreads();

    const __half* Bb = Wp + (size_t)jt * 128 * KW;

    if (wid >= 8) {
        // ================= producers (64 threads) =================
        const int pt = tid - 256;
        for (int ch = 0; ch < NT; ++ch) {
            const int s = ch & 3;
            MBAR_WAIT(sb + s * 16 + 8, ((ch >> 2) & 1) ^ 1);
            const uint32_t ab = sb + OFF_STG + s * STGB, bbs = ab + 16384;
            const int k0 = ch * 64;
#pragma unroll
            for (int i = 0; i < 16; ++i) {
                int idx = pt + i * 64;
                int row = idx >> 3, ck = idx & 7;
                uint32_t sw = sw128(row * 128 + ck * 16);
                const __half* As = (MODE == 1 && k0 >= 512)
                    ? A2 + (size_t)(m0 + row) * LDA + (k0 - 512) + ck * 8
                    : A1 + (size_t)(m0 + row) * LDA + k0 + ck * 8;
                CP16(ab + sw, As);
                CP16(bbs + sw, Bb + (size_t)row * KW + k0 + ck * 8);
            }
            CPA_MBAR(sb + s * 16);
            if (ch == 0 && MODE != 2) {
                if (MODE == 0) {
                    const char* x0src = (const char*)g_x0h + (size_t)tl * 32768;
#pragma unroll
                    for (int i = 0; i < 32; ++i)
                        CP16(sb + OFF_X0 + (pt + i * 64) * 16, x0src + (size_t)(pt + i * 64) * 16);
                }
                const char* csrc = (const char*)(cbuf + (size_t)tl * 4096);
#pragma unroll
                for (int i = 0; i < 16; ++i)
                    CP16(sb + OFF_C + (pt + i * 64) * 16, csrc + (size_t)(pt + i * 64) * 16);
                CPA_MBAR(sb + 64);
            }
        }
        return;
    }

    // ================= consumers (256 threads, warps 0-7) =================
    float acc[4][4][4];
#pragma unroll
    for (int g = 0; g < 4; ++g)
#pragma unroll
        for (int nt = 0; nt < 4; ++nt)
#pragma unroll
            for (int e = 0; e < 4; ++e) acc[g][nt][e] = 0.f;

    const int q = lane >> 3, rr = lane & 7;
    const int arow = wid * 16 + (q & 1) * 8 + rr;
    const int akh  = (q >> 1) * 16;
    const int brow = (q >> 1) * 8 + rr;
    const int bkh  = (q & 1) * 16;

    for (int ch = 0; ch < NT; ++ch) {
        const int s = ch & 3;
        MBAR_WAIT(sb + s * 16, (ch >> 2) & 1);
        const uint32_t ab = sb + OFF_STG + s * STGB, bbs = ab + 16384;
#pragma unroll
        for (int ks = 0; ks < 4; ++ks) {
            uint32_t a0, a1, a2, a3;
            LDSM_X4(a0, a1, a2, a3, ab + sw128(arow * 128 + ks * 32 + akh));
#pragma unroll
            for (int m = 0; m < 8; ++m) {
                uint32_t b0, b1, b2, b3;
                LDSM_X4(b0, b1, b2, b3,
                        bbs + sw128((m * 16 + brow) * 128 + ks * 32 + bkh));
                hmma(acc[m >> 1][(m & 1) * 2 + 0], a0, a1, a2, a3, b0, b1);
                hmma(acc[m >> 1][(m & 1) * 2 + 1], a0, a1, a2, a3, b2, b3);
            }
        }
        MBAR_ARRIVE(sb + s * 16 + 8);
    }

    // compute-warp barrier: all consumers done reading stages -> stage area reusable
    asm volatile("bar.sync 1, 256;" ::: "memory");
    if (MODE != 2) MBAR_WAIT(sb + 64, 0);

    // ---------- epilogue (coalesced; operands in smem) ----------
    float* hs = (float*)(smem + OFF_STG);                // 128 x 33 staging
    const __half* x0s = (const __half*)(smem + OFF_X0);
    const float*  csm = (const float*)(smem + OFF_C);
    const size_t wbase = ((size_t)(tl * 8 + wid) * 16);

#pragma unroll
    for (int nt = 0; nt < 4; ++nt)
#pragma unroll
        for (int r2 = 0; r2 < 2; ++r2)
#pragma unroll
            for (int e = 0; e < 2; ++e) {
                const int grp = (nt * 2 + r2) * 2 + e;
                const int ai  = r2 * 2 + e;
                const int u   = nt * 8 + (lane & 3) * 2 + e;
                float pi = acc[0][nt][ai], pf = acc[1][nt][ai];
                float pg = acc[2][nt][ai], po = acc[3][nt][ai];
                if (MODE == 0) {
                    const __half2* xp = (const __half2*)&x0s[(wid * 16 + grp) * 128 + lane * 4];
                    float2 f01 = __half22float2(xp[0]);
                    float2 f23 = __half22float2(xp[1]);
                    pi += f01.x; pf += f01.y; pg += f23.x; po += f23.y;
                } else {
                    const int ng = jt * 128;
                    pi += addv[ng + u]; pf += addv[ng + 32 + u];
                    pg += addv[ng + 64 + u]; po += addv[ng + 96 + u];
                }
                if (MODE == 2) {
                    __half2 p01 = __floats2half2_rn(pi, pf);
                    __half2 p23 = __floats2half2_rn(pg, po);
                    __half2* xw = (__half2*)&g_x0h[(wbase + grp) * 128 + lane * 4];
                    xw[0] = p01; xw[1] = p23;
                } else {
                    float co = csm[(wid * 16 + grp) * 32 + lane];
                    float cv = sigm(pf) * co + sigm(pi) * tanhf(pg);
                    cbuf[(wbase + grp) * 32 + lane] = cv;
                    const int row_l = wid * 16 + (lane >> 2) + r2 * 8;
                    hs[row_l * 33 + u] = sigm(po) * tanhf(cv);
                }
            }

    if (MODE != 2) {
        asm volatile("bar.sync 1, 256;" ::: "memory");
        __half* hout = (__half*)houtv;
        const int row = tid >> 1, seg = tid & 1;
        __half2 pk[8];
#pragma unroll
        for (int j = 0; j < 8; ++j)
            pk[j] = __floats2half2_rn(hs[row * 33 + seg * 16 + 2 * j],
                                      hs[row * 33 + seg * 16 + 2 * j + 1]);
        uint4* dst = reinterpret_cast<uint4*>(&hout[(size_t)(m0 + row) * HH + jt * 32 + seg * 16]);
        dst[0] = reinterpret_cast<uint4*>(pk)[0];
        dst[1] = reinterpret_cast<uint4*>(pk)[1];
    }
}

__global__ void __launch_bounds__(NTHR, 1) x0_step()
{
    extern __shared__ char smem[];
    tile_body<2>(g_xh, nullptr, g_Wi0p, g_b0p, nullptr, nullptr, smem,
                 blockIdx.x * 128, blockIdx.y, blockIdx.x * 16 + blockIdx.y);
}

// z == 0 -> layer1(t); z == 1 -> layer0(t+1)   (both read h0_rd, independent)
__global__ void __launch_bounds__(NTHR, 1) dual_step(
    const __half* __restrict__ h0_rd, __half* __restrict__ h0_wr,
    const __half* __restrict__ h1_rd, __half* __restrict__ h1_wr, int zoff)
{
    extern __shared__ char smem[];
    const int m0 = blockIdx.x * 128, jt = blockIdx.y;
    const int tl = blockIdx.x * 16 + blockIdx.y;
    if ((int)blockIdx.z + zoff == 0)
        tile_body<1>(h0_rd, h1_rd, g_Wp1, g_b1p, g_c1, h1_wr, smem, m0, jt, tl);
    else
        tile_body<0>(h0_rd, nullptr, g_Wp0, nullptr, g_c0, h0_wr, smem, m0, jt, tl);
}

// ---------- HMMA fc over all timesteps ----------
constexpr int FCSTG = 24576;
constexpr int FCSMEM = 2 * FCSTG;

__global__ void __launch_bounds__(256, 2) fc_mma(
    const __half* __restrict__ h1, const float* __restrict__ fcb,
    float* __restrict__ y2)
{
    extern __shared__ char smem[];
    const uint32_t sb = smem_u32(smem);
    const int tid = threadIdx.x, lane = tid & 31, wid = tid >> 5;
    const size_t m0 = (size_t)blockIdx.x * 128;

    auto copy_stage = [&](int s, int kt) {
        const uint32_t ab = sb + s * FCSTG, bbs = ab + 16384;
        const int k0 = kt * 64;
#pragma unroll
        for (int i = 0; i < 4; ++i) {
            int idx = tid + i * 256;
            int row = idx >> 3, ck = idx & 7;
            uint32_t sw = sw128(row * 128 + ck * 16);
            CP16(ab + sw, h1 + (m0 + row) * HH + k0 + ck * 8);
        }
#pragma unroll
        for (int i = 0; i < 2; ++i) {
            int idx = tid + i * 256;
            int row = idx >> 3, ck = idx & 7;
            uint32_t sw = sw128(row * 128 + ck * 16);
            CP16(bbs + sw, g_fcWh + (size_t)row * HH + k0 + ck * 8);
        }
    };

    float acc[8][4];
#pragma unroll
    for (int n = 0; n < 8; ++n)
#pragma unroll
        for (int e = 0; e < 4; ++e) acc[n][e] = 0.f;

    copy_stage(0, 0); CP_COMMIT();

    const int q = lane >> 3, rr = lane & 7;
    const int arow = wid * 16 + (q & 1) * 8 + rr;
    const int akh  = (q >> 1) * 16;
    const int brow = (q >> 1) * 8 + rr;
    const int bkh  = (q & 1) * 16;

    for (int kt = 0; kt < 8; ++kt) {
        if (kt + 1 < 8) { copy_stage((kt + 1) & 1, kt + 1); CP_COMMIT(); CP_WAIT(1); }
        else CP_WAIT(0);
        __syncthreads();
        const uint32_t ab = sb + (kt & 1) * FCSTG, bbs = ab + 16384;
#pragma unroll
        for (int ks = 0; ks < 4; ++ks) {
            uint32_t a0, a1, a2, a3;
            LDSM_X4(a0, a1, a2, a3, ab + sw128(arow * 128 + ks * 32 + akh));
#pragma unroll
            for (int m = 0; m < 4; ++m) {
                uint32_t b0, b1, b2, b3;
                LDSM_X4(b0, b1, b2, b3,
                        bbs + sw128((m * 16 + brow) * 128 + ks * 32 + bkh));
                hmma(acc[m * 2 + 0], a0, a1, a2, a3, b0, b1);
                hmma(acc[m * 2 + 1], a0, a1, a2, a3, b2, b3);
            }
        }
        __syncthreads();
    }

    const int colb = (lane & 3) * 2;
#pragma unroll
    for (int n = 0; n < 8; ++n) {
        const int col = n * 8 + colb;
        float b0 = fcb[col];
        float b1 = (col + 1 < NJ) ? fcb[col + 1] : 0.f;
#pragma unroll
        for (int r2 = 0; r2 < 2; ++r2) {
            const size_t row = m0 + wid * 16 + (lane >> 2) + r2 * 8;
            *reinterpret_cast<float2*>(&y2[row * 64 + col]) =
                make_float2(acc[n][r2 * 2] + b0, acc[n][r2 * 2 + 1] + b1);
        }
    }
}

// ---------- final transpose [t][b][j](pad64) -> out[b][j][t] ----------
__global__ void transpose_y(const float* __restrict__ gy, float* __restrict__ out)
{
    __shared__ float sy[NSEQ * NJ];
    const int b = blockIdx.x;
    for (int q = threadIdx.x; q < NSEQ * NJ; q += blockDim.x) {
        int t = q / NJ, j = q - t * NJ;
        sy[q] = gy[((size_t)t * NB + b) * 64 + j];
    }
    __syncthreads();
    for (int q = threadIdx.x; q < NSEQ * NJ; q += blockDim.x) {
        int j = q / NSEQ, t = q - j * NSEQ;
        out[(size_t)b * (NJ * NSEQ) + q] = sy[t * NJ + j];
    }
}

// ---------- host ----------
template <typename T>
static void* symaddr(T& sym) {
    void* p = nullptr;
    cudaGetSymbolAddress(&p, sym);
    return p;
}

extern "C" void kernel_launch(void* const* d_in, const int* in_sizes, int n_in,
                              void* d_out, int out_size)
{
    const int*   sl   = (const int*)  d_in[0];
    const int*   el   = (const int*)  d_in[1];
    const float* sc   = (const float*)d_in[2];
    const float* ec   = (const float*)d_in[3];
    const float* emb  = (const float*)d_in[4];
    const float* Wih0 = (const float*)d_in[5];
    const float* Whh0 = (const float*)d_in[6];
    const float* bih0 = (const float*)d_in[7];
    const float* bhh0 = (const float*)d_in[8];
    const float* Wih1 = (const float*)d_in[9];
    const float* Whh1 = (const float*)d_in[10];
    const float* bih1 = (const float*)d_in[11];
    const float* bhh1 = (const float*)d_in[12];
    const float* fcW  = (const float*)d_in[13];
    const float* fcb  = (const float*)d_in[14];
    float* out = (float*)d_out;

    __half* p_h0h = (__half*)symaddr(g_h0h);
    __half* p_h1a = (__half*)symaddr(g_h1a);
    float*  p_y2  = (float*) symaddr(g_y2);

    cudaFuncSetAttribute(x0_step,   cudaFuncAttributeMaxDynamicSharedMemorySize, SMEMSZ);
    cudaFuncSetAttribute(dual_step, cudaFuncAttributeMaxDynamicSharedMemorySize, SMEMSZ);
    cudaFuncSetAttribute(fc_mma,    cudaFuncAttributeMaxDynamicSharedMemorySize, FCSMEM);

    pack_weights<<<256, 256>>>(Wih0, Whh0, bih0, bhh0, Wih1, Whh1, bih1, bhh1, fcW);
    build_x_init<<<256, 256>>>(sl, el, sc, ec, emb);

    const size_t NH = (size_t)NB * HH;
    x0_step<<<dim3(32, 16, 1), NTHR, SMEMSZ>>>();

    // L0(0): reads h0h[0] (zeros), writes h0h[1]
    dual_step<<<dim3(32, 16, 1), NTHR, SMEMSZ>>>(p_h0h, p_h0h + NH, nullptr, nullptr, 1);

    for (int t = 0; t < NSEQ - 1; ++t) {
        const int src = (t & 1) ^ 1;
        dual_step<<<dim3(32, 16, 2), NTHR, SMEMSZ>>>(
            p_h0h + (size_t)src * NH,
            p_h0h + (size_t)(t & 1) * NH,
            p_h1a + (size_t)t * NH,
            p_h1a + (size_t)(t + 1) * NH, 0);
    }
    dual_step<<<dim3(32, 16, 1), NTHR, SMEMSZ>>>(
        p_h0h, nullptr, p_h1a + (size_t)(NSEQ - 1) * NH, p_h1a + (size_t)NSEQ * NH, 0);

    fc_mma<<<NSEQ * NB / 128, 256, FCSMEM>>>(p_h1a + NH, fcb, p_y2);
    transpose_y<<<NB, 256>>>(p_y2, out);
}

// round 14
// speedup vs baseline: 1.1644x; 1.1644x over previous
#include <cuda_runtime.h>
#include <cuda_fp16.h>
#include <cstdint>
#include <cstddef>

#define NB 4096
#define HH 512
#define NSEQ 100
#define NJ 63

// ---------- device scratch ----------
__device__ __align__(1024) __half g_xh [NB * 256];
__device__ __align__(1024) __half g_h0h[2][NB * HH];
__device__ __align__(1024) __half g_h1a[(size_t)(NSEQ + 1) * NB * HH];
__device__ __align__(1024) float  g_c0 [NB * HH];          // tile-order layout
__device__ __align__(1024) float  g_c1 [NB * HH];          // tile-order layout
__device__ __align__(1024) __half g_Wi0p[16 * 128 * 256];
__device__ __align__(1024) __half g_Wp0 [16 * 128 * 512];
__device__ __align__(1024) __half g_Wp1 [16 * 128 * 1024];
__device__ __align__(1024) __half g_fcWh[64 * 512];
__device__ float g_b0p[2048];
__device__ float g_b1p[2048];
__device__ __align__(1024) __half g_x0h[(size_t)2048 * NB]; // epi-order halves
__device__ float g_y2[(size_t)NSEQ * NB * 64];

// ---------- helpers ----------
__device__ __forceinline__ float sigm(float x) { return 1.f / (1.f + expf(-x)); }
__device__ __forceinline__ uint32_t smem_u32(const void* p) {
    uint32_t a;
    asm("{ .reg .u64 t; cvta.to.shared.u64 t, %1; cvt.u32.u64 %0, t; }" : "=r"(a) : "l"(p));
    return a;
}
#define CP16(dst, src) asm volatile("cp.async.cg.shared.global [%0], [%1], 16;" :: "r"((uint32_t)(dst)), "l"(src) : "memory")
#define CP_COMMIT()    asm volatile("cp.async.commit_group;" ::: "memory")
#define CP_WAIT(n)     asm volatile("cp.async.wait_group %0;" :: "n"(n) : "memory")
#define LDSM_X4(r0, r1, r2, r3, a) \
    asm volatile("ldmatrix.sync.aligned.m8n8.x4.shared.b16 {%0,%1,%2,%3}, [%4];" \
        : "=r"(r0), "=r"(r1), "=r"(r2), "=r"(r3) : "r"(a))

__device__ __forceinline__ void hmma(float (&c)[4],
    uint32_t a0, uint32_t a1, uint32_t a2, uint32_t a3, uint32_t b0, uint32_t b1)
{
    asm volatile(
        "mma.sync.aligned.m16n8k16.row.col.f32.f16.f16.f32 "
        "{%0,%1,%2,%3}, {%4,%5,%6,%7}, {%8,%9}, {%0,%1,%2,%3};\n"
        : "+f"(c[0]), "+f"(c[1]), "+f"(c[2]), "+f"(c[3])
        : "r"(a0), "r"(a1), "r"(a2), "r"(a3), "r"(b0), "r"(b1));
}
__device__ __forceinline__ uint32_t sw128(uint32_t off) { return off ^ ((off >> 3) & 0x70); }

// ---------- prologue: col n of tile jt -> orig row (n>>5)*512 + jt*32 + (n&31) ----------
__global__ void pack_weights(
    const float* __restrict__ Wih0, const float* __restrict__ Whh0,
    const float* __restrict__ bih0, const float* __restrict__ bhh0,
    const float* __restrict__ Wih1, const float* __restrict__ Whh1,
    const float* __restrict__ bih1, const float* __restrict__ bhh1,
    const float* __restrict__ fcW)
{
    int i0 = blockIdx.x * blockDim.x + threadIdx.x;
    int st = gridDim.x * blockDim.x;
    for (int i = i0; i < 16 * 128 * 512; i += st) {
        int jt = i >> 16, n = (i >> 9) & 127, k = i & 511;
        int row = (n >> 5) * HH + jt * 32 + (n & 31);
        g_Wp0[i] = __float2half_rn(Whh0[(size_t)row * HH + k]);
    }
    for (int i = i0; i < 16 * 128 * 1024; i += st) {
        int jt = i >> 17, n = (i >> 10) & 127, k = i & 1023;
        int row = (n >> 5) * HH + jt * 32 + (n & 31);
        float v = (k < HH) ? Wih1[(size_t)row * HH + k] : Whh1[(size_t)row * HH + k - HH];
        g_Wp1[i] = __float2half_rn(v);
    }
    for (int i = i0; i < 16 * 128 * 256; i += st) {
        int jt = i >> 15, n = (i >> 8) & 127, k = i & 255;
        int row = (n >> 5) * HH + jt * 32 + (n & 31);
        g_Wi0p[i] = (k < 254) ? __float2half_rn(Wih0[(size_t)row * 254 + k]) : __half(0);
    }
    for (int i = i0; i < 64 * 512; i += st) {
        int j = i >> 9, k = i & 511;
        g_fcWh[i] = (j < NJ) ? __float2half_rn(fcW[(size_t)j * HH + k]) : __half(0);
    }
    for (int i = i0; i < 2048; i += st) {
        int jt = i >> 7, n = i & 127;
        int row = (n >> 5) * HH + jt * 32 + (n & 31);
        g_b0p[i] = bih0[row] + bhh0[row];
        g_b1p[i] = bih1[row] + bhh1[row];
    }
}

__global__ void build_x_init(
    const int* __restrict__ sl, const int* __restrict__ el,
    const float* __restrict__ sc, const float* __restrict__ ec,
    const float* __restrict__ emb)
{
    int i0 = blockIdx.x * blockDim.x + threadIdx.x;
    int st = gridDim.x * blockDim.x;
    for (int i = i0; i < NB * 256; i += st) {
        int b = i >> 8, k = i & 255;
        float v;
        if      (k < 64)  v = emb[sl[b] * 64 + k];
        else if (k < 128) v = emb[el[b] * 64 + (k - 64)];
        else if (k < 191) v = sc[b * 63 + (k - 128)];
        else if (k < 254) v = ec[b * 63 + (k - 191)];
        else              v = 0.f;
        g_xh[i] = __float2half_rn(v);
    }
    __half z = __half(0);
    for (int i = i0; i < NB * HH; i += st) {
        g_h0h[0][i] = z; g_h0h[1][i] = z; g_h1a[i] = z;
        g_c0[i] = 0.f; g_c1[i] = 0.f;
    }
}

// ---------- fused GEMM + gates ----------
// CTA 128x128 (cols = 4 gates x 32 units, gate-separated), 256 threads, 8 warps;
// warp tile 16 rows x 128 cols (all 4 gates in-thread). 2-stage cp.async pipeline.
// Epilogue operands (x0 fp16 slice 32KB + c fp32 slice 16KB) prefetched via cp.async
// with chunk-1's commit group. Inner loop: ALL 9 LDSM issued up front (MLP=9),
// then 16 HMMA streamed -> breaks the LDSM->HMMA serial dependency chain.
constexpr int STG   = 32768;
constexpr int EPIX0 = 65536;
constexpr int EPIC  = 98304;
constexpr int SMEMSZ = 114688;

template<int MODE>   // 0: layer0 K=512 (+x0)  1: layer1 K=1024 (+bias)  2: x0 K=256 (+bias)
__device__ __forceinline__ void tile_body(
    const __half* __restrict__ A1, const __half* __restrict__ A2,
    const __half* __restrict__ Wp, const float* __restrict__ addv,
    float* __restrict__ cbuf, void* __restrict__ houtv, char* smem,
    int m0, int jt, int tl)
{
    const uint32_t sb = smem_u32(smem);
    const int tid = threadIdx.x, lane = tid & 31, wid = tid >> 5;
    constexpr int KW  = (MODE == 0) ? 512 : (MODE == 1) ? 1024 : 256;
    constexpr int LDA = (MODE == 2) ? 256 : 512;
    constexpr int NT  = KW / 64;

    const __half* Bb = Wp + (size_t)jt * 128 * KW;

    auto copy_stage = [&](int s, int kt) {
        const uint32_t ab = sb + s * STG, bbs = ab + 16384;
        const int k0 = kt * 64;
#pragma unroll
        for (int i = 0; i < 4; ++i) {
            int idx = tid + i * 256;
            int row = idx >> 3, ck = idx & 7;
            uint32_t sw = sw128(row * 128 + ck * 16);
            const __half* As = (MODE == 1 && k0 >= 512)
                ? A2 + (size_t)(m0 + row) * LDA + (k0 - 512) + ck * 8
                : A1 + (size_t)(m0 + row) * LDA + k0 + ck * 8;
            CP16(ab + sw, As);
            CP16(bbs + sw, Bb + (size_t)row * KW + k0 + ck * 8);
        }
    };
    auto copy_epi = [&]() {
        if (MODE == 0) {
            const char* x0src = (const char*)g_x0h + (size_t)tl * 32768;
#pragma unroll
            for (int i = 0; i < 8; ++i)
                CP16(sb + EPIX0 + (tid + i * 256) * 16, x0src + (size_t)(tid + i * 256) * 16);
        }
        if (MODE != 2) {
            const char* csrc = (const char*)(cbuf + (size_t)tl * 4096);
#pragma unroll
            for (int i = 0; i < 4; ++i)
                CP16(sb + EPIC + (tid + i * 256) * 16, csrc + (size_t)(tid + i * 256) * 16);
        }
    };

    float acc[4][4][4];
#pragma unroll
    for (int g = 0; g < 4; ++g)
#pragma unroll
        for (int nt = 0; nt < 4; ++nt)
#pragma unroll
            for (int e = 0; e < 4; ++e) acc[g][nt][e] = 0.f;

    copy_stage(0, 0); CP_COMMIT();

    const int q = lane >> 3, rr = lane & 7;
    const int arow = wid * 16 + (q & 1) * 8 + rr;
    const int akh  = (q >> 1) * 16;
    const int brow = (q >> 1) * 8 + rr;
    const int bkh  = (q & 1) * 16;

    for (int kt = 0; kt < NT; ++kt) {
        if (kt + 1 < NT) {
            if (kt == 0) copy_epi();
            copy_stage((kt + 1) & 1, kt + 1);
            CP_COMMIT();
            CP_WAIT(1);
        } else {
            CP_WAIT(0);
        }
        __syncthreads();
        const uint32_t ab = sb + (kt & 1) * STG, bbs = ab + 16384;
#pragma unroll
        for (int ks = 0; ks < 4; ++ks) {
            uint32_t a0, a1, a2, a3;
            uint32_t bf[8][4];
            LDSM_X4(a0, a1, a2, a3, ab + sw128(arow * 128 + ks * 32 + akh));
#pragma unroll
            for (int m = 0; m < 8; ++m)
                LDSM_X4(bf[m][0], bf[m][1], bf[m][2], bf[m][3],
                        bbs + sw128((m * 16 + brow) * 128 + ks * 32 + bkh));
#pragma unroll
            for (int m = 0; m < 8; ++m) {
                hmma(acc[m >> 1][(m & 1) * 2 + 0], a0, a1, a2, a3, bf[m][0], bf[m][1]);
                hmma(acc[m >> 1][(m & 1) * 2 + 1], a0, a1, a2, a3, bf[m][2], bf[m][3]);
            }
        }
        __syncthreads();
    }

    // ---------- epilogue (coalesced; epi operands in smem) ----------
    float* hs = (float*)smem;                            // 128 x 33 staging (stage area)
    const __half* x0s = (const __half*)(smem + EPIX0);
    const float*  csm = (const float*)(smem + EPIC);
    const size_t wbase = ((size_t)(tl * 8 + wid) * 16);

#pragma unroll
    for (int nt = 0; nt < 4; ++nt)
#pragma unroll
        for (int r2 = 0; r2 < 2; ++r2)
#pragma unroll
            for (int e = 0; e < 2; ++e) {
                const int grp = (nt * 2 + r2) * 2 + e;
                const int ai  = r2 * 2 + e;
                const int u   = nt * 8 + (lane & 3) * 2 + e;
                float pi = acc[0][nt][ai], pf = acc[1][nt][ai];
                float pg = acc[2][nt][ai], po = acc[3][nt][ai];
                if (MODE == 0) {
                    const __half2* xp = (const __half2*)&x0s[(wid * 16 + grp) * 128 + lane * 4];
                    float2 f01 = __half22float2(xp[0]);
                    float2 f23 = __half22float2(xp[1]);
                    pi += f01.x; pf += f01.y; pg += f23.x; po += f23.y;
                } else {
                    const int ng = jt * 128;
                    pi += addv[ng + u]; pf += addv[ng + 32 + u];
                    pg += addv[ng + 64 + u]; po += addv[ng + 96 + u];
                }
                if (MODE == 2) {
                    __half2 p01 = __floats2half2_rn(pi, pf);
                    __half2 p23 = __floats2half2_rn(pg, po);
                    __half2* xw = (__half2*)&g_x0h[(wbase + grp) * 128 + lane * 4];
                    xw[0] = p01; xw[1] = p23;
                } else {
                    float co = csm[(wid * 16 + grp) * 32 + lane];
                    float cv = sigm(pf) * co + sigm(pi) * tanhf(pg);
                    cbuf[(wbase + grp) * 32 + lane] = cv;
                    const int row_l = wid * 16 + (lane >> 2) + r2 * 8;
                    hs[row_l * 33 + u] = sigm(po) * tanhf(cv);
                }
            }

    if (MODE != 2) {
        __syncthreads();
        __half* hout = (__half*)houtv;
        const int row = tid >> 1, seg = tid & 1;
        __half2 pk[8];
#pragma unroll
        for (int j = 0; j < 8; ++j)
            pk[j] = __floats2half2_rn(hs[row * 33 + seg * 16 + 2 * j],
                                      hs[row * 33 + seg * 16 + 2 * j + 1]);
        uint4* dst = reinterpret_cast<uint4*>(&hout[(size_t)(m0 + row) * HH + jt * 32 + seg * 16]);
        dst[0] = reinterpret_cast<uint4*>(pk)[0];
        dst[1] = reinterpret_cast<uint4*>(pk)[1];
        __syncthreads();
    }
}

__global__ void __launch_bounds__(256, 2) x0_step()
{
    extern __shared__ char smem[];
    tile_body<2>(g_xh, nullptr, g_Wi0p, g_b0p, nullptr, nullptr, smem,
                 blockIdx.x * 128, blockIdx.y, blockIdx.x * 16 + blockIdx.y);
}

// z == 0 -> layer1(t); z == 1 -> layer0(t+1)   (both read h0_rd, independent)
__global__ void __launch_bounds__(256, 2) dual_step(
    const __half* __restrict__ h0_rd, __half* __restrict__ h0_wr,
    const __half* __restrict__ h1_rd, __half* __restrict__ h1_wr, int zoff)
{
    extern __shared__ char smem[];
    const int m0 = blockIdx.x * 128, jt = blockIdx.y;
    const int tl = blockIdx.x * 16 + blockIdx.y;
    if ((int)blockIdx.z + zoff == 0)
        tile_body<1>(h0_rd, h1_rd, g_Wp1, g_b1p, g_c1, h1_wr, smem, m0, jt, tl);
    else
        tile_body<0>(h0_rd, nullptr, g_Wp0, nullptr, g_c0, h0_wr, smem, m0, jt, tl);
}

// ---------- HMMA fc over all timesteps: y2[409600 x 64] = h1 @ fcW^T + fcb ----------
constexpr int FCSTG = 24576;
constexpr int FCSMEM = 2 * FCSTG;

__global__ void __launch_bounds__(256, 2) fc_mma(
    const __half* __restrict__ h1, const float* __restrict__ fcb,
    float* __restrict__ y2)
{
    extern __shared__ char smem[];
    const uint32_t sb = smem_u32(smem);
    const int tid = threadIdx.x, lane = tid & 31, wid = tid >> 5;
    const size_t m0 = (size_t)blockIdx.x * 128;

    auto copy_stage = [&](int s, int kt) {
        const uint32_t ab = sb + s * FCSTG, bbs = ab + 16384;
        const int k0 = kt * 64;
#pragma unroll
        for (int i = 0; i < 4; ++i) {
            int idx = tid + i * 256;
            int row = idx >> 3, ck = idx & 7;
            uint32_t sw = sw128(row * 128 + ck * 16);
            CP16(ab + sw, h1 + (m0 + row) * HH + k0 + ck * 8);
        }
#pragma unroll
        for (int i = 0; i < 2; ++i) {
            int idx = tid + i * 256;
            int row = idx >> 3, ck = idx & 7;
            uint32_t sw = sw128(row * 128 + ck * 16);
            CP16(bbs + sw, g_fcWh + (size_t)row * HH + k0 + ck * 8);
        }
    };

    float acc[8][4];
#pragma unroll
    for (int n = 0; n < 8; ++n)
#pragma unroll
        for (int e = 0; e < 4; ++e) acc[n][e] = 0.f;

    copy_stage(0, 0); CP_COMMIT();

    const int q = lane >> 3, rr = lane & 7;
    const int arow = wid * 16 + (q & 1) * 8 + rr;
    const int akh  = (q >> 1) * 16;
    const int brow = (q >> 1) * 8 + rr;
    const int bkh  = (q & 1) * 16;

    for (int kt = 0; kt < 8; ++kt) {
        if (kt + 1 < 8) { copy_stage((kt + 1) & 1, kt + 1); CP_COMMIT(); CP_WAIT(1); }
        else CP_WAIT(0);
        __syncthreads();
        const uint32_t ab = sb + (kt & 1) * FCSTG, bbs = ab + 16384;
#pragma unroll
        for (int ks = 0; ks < 4; ++ks) {
            uint32_t a0, a1, a2, a3;
            uint32_t bf[4][4];
            LDSM_X4(a0, a1, a2, a3, ab + sw128(arow * 128 + ks * 32 + akh));
#pragma unroll
            for (int m = 0; m < 4; ++m)
                LDSM_X4(bf[m][0], bf[m][1], bf[m][2], bf[m][3],
                        bbs + sw128((m * 16 + brow) * 128 + ks * 32 + bkh));
#pragma unroll
            for (int m = 0; m < 4; ++m) {
                hmma(acc[m * 2 + 0], a0, a1, a2, a3, bf[m][0], bf[m][1]);
                hmma(acc[m * 2 + 1], a0, a1, a2, a3, bf[m][2], bf[m][3]);
            }
        }
        __syncthreads();
    }

    const int colb = (lane & 3) * 2;
#pragma unroll
    for (int n = 0; n < 8; ++n) {
        const int col = n * 8 + colb;
        float b0 = fcb[col];
        float b1 = (col + 1 < NJ) ? fcb[col + 1] : 0.f;
#pragma unroll
        for (int r2 = 0; r2 < 2; ++r2) {
            const size_t row = m0 + wid * 16 + (lane >> 2) + r2 * 8;
            *reinterpret_cast<float2*>(&y2[row * 64 + col]) =
                make_float2(acc[n][r2 * 2] + b0, acc[n][r2 * 2 + 1] + b1);
        }
    }
}

// ---------- final transpose [t][b][j](pad64) -> out[b][j][t] ----------
__global__ void transpose_y(const float* __restrict__ gy, float* __restrict__ out)
{
    __shared__ float sy[NSEQ * NJ];
    const int b = blockIdx.x;
    for (int q = threadIdx.x; q < NSEQ * NJ; q += blockDim.x) {
        int t = q / NJ, j = q - t * NJ;
        sy[q] = gy[((size_t)t * NB + b) * 64 + j];
    }
    __syncthreads();
    for (int q = threadIdx.x; q < NSEQ * NJ; q += blockDim.x) {
        int j = q / NSEQ, t = q - j * NSEQ;
        out[(size_t)b * (NJ * NSEQ) + q] = sy[t * NJ + j];
    }
}

// ---------- host ----------
template <typename T>
static void* symaddr(T& sym) {
    void* p = nullptr;
    cudaGetSymbolAddress(&p, sym);
    return p;
}

extern "C" void kernel_launch(void* const* d_in, const int* in_sizes, int n_in,
                              void* d_out, int out_size)
{
    const int*   sl   = (const int*)  d_in[0];
    const int*   el   = (const int*)  d_in[1];
    const float* sc   = (const float*)d_in[2];
    const float* ec   = (const float*)d_in[3];
    const float* emb  = (const float*)d_in[4];
    const float* Wih0 = (const float*)d_in[5];
    const float* Whh0 = (const float*)d_in[6];
    const float* bih0 = (const float*)d_in[7];
    const float* bhh0 = (const float*)d_in[8];
    const float* Wih1 = (const float*)d_in[9];
    const float* Whh1 = (const float*)d_in[10];
    const float* bih1 = (const float*)d_in[11];
    const float* bhh1 = (const float*)d_in[12];
    const float* fcW  = (const float*)d_in[13];
    const float* fcb  = (const float*)d_in[14];
    float* out = (float*)d_out;

    __half* p_h0h = (__half*)symaddr(g_h0h);
    __half* p_h1a = (__half*)symaddr(g_h1a);
    float*  p_y2  = (float*) symaddr(g_y2);

    cudaFuncSetAttribute(x0_step,   cudaFuncAttributeMaxDynamicSharedMemorySize, SMEMSZ);
    cudaFuncSetAttribute(dual_step, cudaFuncAttributeMaxDynamicSharedMemorySize, SMEMSZ);
    cudaFuncSetAttribute(fc_mma,    cudaFuncAttributeMaxDynamicSharedMemorySize, FCSMEM);

    pack_weights<<<256, 256>>>(Wih0, Whh0, bih0, bhh0, Wih1, Whh1, bih1, bhh1, fcW);
    build_x_init<<<256, 256>>>(sl, el, sc, ec, emb);

    const size_t NH = (size_t)NB * HH;
    x0_step<<<dim3(32, 16, 1), 256, SMEMSZ>>>();

    // L0(0): reads h0h[0] (zeros), writes h0h[1]
    dual_step<<<dim3(32, 16, 1), 256, SMEMSZ>>>(p_h0h, p_h0h + NH, nullptr, nullptr, 1);

    for (int t = 0; t < NSEQ - 1; ++t) {
        const int src = (t & 1) ^ 1;
        dual_step<<<dim3(32, 16, 2), 256, SMEMSZ>>>(
            p_h0h + (size_t)src * NH,
            p_h0h + (size_t)(t & 1) * NH,
            p_h1a + (size_t)t * NH,
            p_h1a + (size_t)(t + 1) * NH, 0);
    }
    dual_step<<<dim3(32, 16, 1), 256, SMEMSZ>>>(
        p_h0h, nullptr, p_h1a + (size_t)(NSEQ - 1) * NH, p_h1a + (size_t)NSEQ * NH, 0);

    fc_mma<<<NSEQ * NB / 128, 256, FCSMEM>>>(p_h1a + NH, fcb, p_y2);
    transpose_y<<<NB, 256>>>(p_y2, out);
}